// round 7
// baseline (speedup 1.0000x reference)
#include <cuda_runtime.h>
#include <math.h>
#include <stdint.h>

#define BB 8
#define LL 4096
#define DD 256
#define ML (BB*LL)          // 32768 rows
#define KVS 8               // split-K for kv (deterministic)

#define APJ 20              // proj/out A smem stride ([m][k], 16 k + 4 pad)
#define AKV 136             // kv A smem stride ([k][m], 128 + 8 pad)
#define BN  264             // B smem stride ([k][n], 256 + 8 pad) - conflict-free

// ---- scratch (device globals; no allocations allowed) ----
__device__ float g_Q[ML*DD];       // tf32-pre-rounded
__device__ float g_K[ML*DD];       // tf32-pre-rounded
__device__ float g_V[ML*DD];       // tf32-pre-rounded
__device__ float g_Wr[3*DD*DD];    // rounded weights [w][k][n] (w: 0=q,1=k,2=v)
__device__ float g_kvpart[KVS*BB*DD*DD];
__device__ float g_kv[BB*DD*DD];   // rounded, natural [d][h] = [k][n] for out
__device__ float g_kcs[256*DD];    // K colsum partials per 128-row block
__device__ float g_ksum[BB*DD];
__device__ float g_z[ML];

// ---- helpers ----
__device__ __forceinline__ uint32_t f2tf(float x) {
    uint32_t r; asm("cvt.rna.tf32.f32 %0, %1;" : "=r"(r) : "f"(x)); return r;
}
__device__ __forceinline__ void mma8(float* d, const uint32_t* a, const uint32_t* b) {
    asm volatile(
        "mma.sync.aligned.m16n8k8.row.col.f32.tf32.tf32.f32 "
        "{%0,%1,%2,%3}, {%4,%5,%6,%7}, {%8,%9}, {%0,%1,%2,%3};\n"
        : "+f"(d[0]), "+f"(d[1]), "+f"(d[2]), "+f"(d[3])
        : "r"(a[0]), "r"(a[1]), "r"(a[2]), "r"(a[3]), "r"(b[0]), "r"(b[1]));
}
__device__ __forceinline__ void cp16(uint32_t saddr, const void* g) {
    asm volatile("cp.async.cg.shared.global [%0], [%1], 16;\n"
                 :: "r"(saddr), "l"(g) : "memory");
}
#define CP_COMMIT() asm volatile("cp.async.commit_group;\n" ::: "memory")
#define CP_WAIT1()  asm volatile("cp.async.wait_group 1;\n" ::: "memory")
#define CP_WAIT0()  asm volatile("cp.async.wait_group 0;\n" ::: "memory")

// ============================================================
// Weight pre-round: g_Wr[w][k][n] = round(W_w[k][n])
// ============================================================
__global__ void prep_w(const float* __restrict__ Wq, const float* __restrict__ Wk,
                       const float* __restrict__ Wv)
{
    const int kk = blockIdx.x;
    const int w  = blockIdx.y;
    const int n  = threadIdx.x;
    const float* W = (w == 0) ? Wq : (w == 1) ? Wk : Wv;
    g_Wr[(size_t)w * DD * DD + (size_t)kk * DD + n] =
        __uint_as_float(f2tf(W[(size_t)kk * DD + n]));
}

// ============================================================
// Projection, CTA tile 128x256 (full N), warp tile 64x64, 8 warps.
// mode 0: V (no act). mode 1: K (act + colsum). mode 2: Q (act + z).
// A cvt at fragment load (X raw); B pre-rounded (g_Wr).
// smem (dynamic floats): As 2x128x20 @0, Bs 2x16x264 @5120
// ============================================================
__global__ __launch_bounds__(256)
void proj_g(const float* __restrict__ Xv, const float* __restrict__ Xk,
            const float* __restrict__ Xq,
            const float* __restrict__ bv, const float* __restrict__ bk,
            const float* __restrict__ bq, int qmode)
{
    extern __shared__ __align__(16) float sm[];
    float* As = sm;                 // 2 * 2560
    float* Bs = sm + 5120;          // 2 * 4224
    float* scr = sm;                // epilogue staging (aliases As)

    const int tid  = threadIdx.x;
    const int sel  = qmode ? 2 : blockIdx.z;      // 0=V,1=K,2=Q
    const int row0 = blockIdx.x * 128;
    const int mtile = blockIdx.x;

    const float* X    = (sel == 0) ? Xv : (sel == 1) ? Xk : Xq;
    const float* bias = (sel == 0) ? bv : (sel == 1) ? bk : bq;
    const float* W    = g_Wr + (size_t)((sel == 0) ? 2 : (sel == 1) ? 1 : 0) * DD * DD;
    float* Y          = (sel == 0) ? g_V : (sel == 1) ? g_K : g_Q;

    const int warp = tid >> 5, lane = tid & 31;
    const int wm = warp & 1, wn = warp >> 1;     // 2 x 4 warps
    const int lr = lane >> 2, lc = lane & 3;

    // A loader: 2 cp16 -> As[row][koff..koff+8)
    const int a_r = tid >> 1, a_k = (tid & 1) * 8;
    // B loader: 4 cp16 -> Bs[row][bc..bc+16)
    const int b_r = tid >> 4, b_c = (tid & 15) * 16;

    const float* Ag = X + (size_t)(row0 + a_r) * DD + a_k;
    const float* Bg = W + (size_t)b_r * DD + b_c;

    const uint32_t sA = (uint32_t)__cvta_generic_to_shared(As);
    const uint32_t sB = (uint32_t)__cvta_generic_to_shared(Bs);

    float acc[4][8][4] = {};

    #define P_ISSUE(st, k0) do {                                               \
        cp16(sA + ((st)*2560 + a_r*APJ + a_k) * 4,     Ag + (k0));             \
        cp16(sA + ((st)*2560 + a_r*APJ + a_k + 4) * 4, Ag + (k0) + 4);         \
        const float* _bg = Bg + (size_t)(k0) * DD;                             \
        cp16(sB + ((st)*4224 + b_r*BN + b_c) * 4,      _bg);                   \
        cp16(sB + ((st)*4224 + b_r*BN + b_c + 4) * 4,  _bg + 4);               \
        cp16(sB + ((st)*4224 + b_r*BN + b_c + 8) * 4,  _bg + 8);               \
        cp16(sB + ((st)*4224 + b_r*BN + b_c + 12) * 4, _bg + 12);              \
    } while (0)

    P_ISSUE(0, 0);  CP_COMMIT();
    P_ISSUE(1, 16); CP_COMMIT();

    const int NST = DD / 16;   // 16
    for (int s = 0; s < NST; s++) {
        const int cur = s & 1;
        if (s + 1 < NST) CP_WAIT1(); else CP_WAIT0();
        __syncthreads();
        const float* a0 = As + cur * 2560;
        const float* bgs = Bs + cur * 4224;
        #pragma unroll
        for (int ks = 0; ks < 2; ks++) {
            const int kb = ks * 8;
            uint32_t af[4][4], bf[8][2];
            #pragma unroll
            for (int mt = 0; mt < 4; mt++) {
                const int m = wm * 64 + mt * 16 + lr;
                af[mt][0] = f2tf(a0[(m)     * APJ + kb + lc]);
                af[mt][1] = f2tf(a0[(m + 8) * APJ + kb + lc]);
                af[mt][2] = f2tf(a0[(m)     * APJ + kb + lc + 4]);
                af[mt][3] = f2tf(a0[(m + 8) * APJ + kb + lc + 4]);
            }
            #pragma unroll
            for (int nt = 0; nt < 8; nt++) {
                const int n = wn * 64 + nt * 8 + lr;
                bf[nt][0] = __float_as_uint(bgs[(kb + lc)     * BN + n]);
                bf[nt][1] = __float_as_uint(bgs[(kb + 4 + lc) * BN + n]);
            }
            #pragma unroll
            for (int mt = 0; mt < 4; mt++)
                #pragma unroll
                for (int nt = 0; nt < 8; nt++)
                    mma8(acc[mt][nt], af[mt], bf[nt]);
        }
        __syncthreads();
        if (s + 2 < NST) { P_ISSUE(cur, (s + 2) * 16); CP_COMMIT(); }
    }
    #undef P_ISSUE

    // ---- epilogue ----
    const int bbatch = row0 >> 12;
    float cs[8][2];
    float za[4][2];
    if (sel == 1) {
        #pragma unroll
        for (int nt = 0; nt < 8; nt++) { cs[nt][0] = 0.f; cs[nt][1] = 0.f; }
    }
    if (sel == 2) {
        #pragma unroll
        for (int mt = 0; mt < 4; mt++) { za[mt][0] = 0.f; za[mt][1] = 0.f; }
    }

    #pragma unroll
    for (int mt = 0; mt < 4; mt++) {
        const int r0 = row0 + wm * 64 + mt * 16 + lr;
        #pragma unroll
        for (int nt = 0; nt < 8; nt++) {
            const int c = wn * 64 + nt * 8 + 2 * lc;
            const float b0 = __ldg(&bias[c]), b1 = __ldg(&bias[c + 1]);
            float v0 = acc[mt][nt][0] + b0;
            float v1 = acc[mt][nt][1] + b1;
            float v2 = acc[mt][nt][2] + b0;
            float v3 = acc[mt][nt][3] + b1;
            if (sel != 0) {   // elu+1
                v0 = (v0 > 0.0f) ? (v0 + 1.0f) : __expf(v0);
                v1 = (v1 > 0.0f) ? (v1 + 1.0f) : __expf(v1);
                v2 = (v2 > 0.0f) ? (v2 + 1.0f) : __expf(v2);
                v3 = (v3 > 0.0f) ? (v3 + 1.0f) : __expf(v3);
            }
            if (sel == 1) {
                cs[nt][0] += v0 + v2;
                cs[nt][1] += v1 + v3;
            }
            if (sel == 2) {
                const float k0v = __ldg(&g_ksum[bbatch * DD + c]);
                const float k1v = __ldg(&g_ksum[bbatch * DD + c + 1]);
                za[mt][0] = fmaf(v0, k0v, fmaf(v1, k1v, za[mt][0]));
                za[mt][1] = fmaf(v2, k0v, fmaf(v3, k1v, za[mt][1]));
            }
            float2 p0 = { __uint_as_float(f2tf(v0)), __uint_as_float(f2tf(v1)) };
            float2 p1 = { __uint_as_float(f2tf(v2)), __uint_as_float(f2tf(v3)) };
            *(float2*)&Y[(size_t)r0 * DD + c]       = p0;
            *(float2*)&Y[(size_t)(r0 + 8) * DD + c] = p1;
        }
    }

    if (sel == 1) {
        // reduce over lr; lanes with same lc hold warp column sums
        #pragma unroll
        for (int nt = 0; nt < 8; nt++) {
            #pragma unroll
            for (int off = 4; off < 32; off <<= 1) {
                cs[nt][0] += __shfl_xor_sync(0xffffffffu, cs[nt][0], off);
                cs[nt][1] += __shfl_xor_sync(0xffffffffu, cs[nt][1], off);
            }
        }
        if (lr == 0) {
            #pragma unroll
            for (int nt = 0; nt < 8; nt++) {
                const int c = wn * 64 + nt * 8 + 2 * lc;
                scr[wm * 256 + c]     = cs[nt][0];
                scr[wm * 256 + c + 1] = cs[nt][1];
            }
        }
        __syncthreads();
        g_kcs[(size_t)mtile * DD + tid] = scr[tid] + scr[256 + tid];
    }
    if (sel == 2) {
        // reduce over lc, then across 4 n-warps via smem
        #pragma unroll
        for (int mt = 0; mt < 4; mt++) {
            #pragma unroll
            for (int off = 1; off < 4; off <<= 1) {
                za[mt][0] += __shfl_xor_sync(0xffffffffu, za[mt][0], off);
                za[mt][1] += __shfl_xor_sync(0xffffffffu, za[mt][1], off);
            }
        }
        if (lc == 0) {
            #pragma unroll
            for (int mt = 0; mt < 4; mt++) {
                const int rl = wm * 64 + mt * 16 + lr;
                scr[wn * 128 + rl]     = za[mt][0];
                scr[wn * 128 + rl + 8] = za[mt][1];
            }
        }
        __syncthreads();
        if (tid < 128)
            g_z[row0 + tid] = scr[tid] + scr[128 + tid] + scr[256 + tid]
                            + scr[384 + tid] + 1e-6f;
    }
}

// ksum[b,d] = sum over 32 row-blocks of g_kcs
__global__ void reduce_kcs_kernel()
{
    int i = blockIdx.x * blockDim.x + threadIdx.x;
    if (i >= BB * DD) return;
    int b = i / DD, d = i % DD;
    float s = 0.0f;
    #pragma unroll
    for (int j = 0; j < 32; j++)
        s += g_kcs[(size_t)(b * 32 + j) * DD + d];
    g_ksum[i] = s;
}

// ============================================================
// kv split-K: kvpart[bz][d,h] = sum_{l in chunk} K[l,d] V[l,h]
// CTA tile d128 x h256, warp tile 64x64, inputs pre-rounded.
// grid = (2 dtiles, BB*KVS). smem: As 2x16x136 @0, Bs 2x16x264 @4352
// ============================================================
__global__ __launch_bounds__(256)
void kv_g()
{
    extern __shared__ __align__(16) float sm[];
    float* As = sm;                 // 2 * 2176
    float* Bs = sm + 4352;          // 2 * 4224

    const int tid = threadIdx.x;
    const int d0 = blockIdx.x * 128;
    const int bz = blockIdx.y;
    const int b  = bz / KVS;
    const int sp = bz % KVS;
    const int lchunk = LL / KVS;      // 512
    const size_t base = ((size_t)b * LL + (size_t)sp * lchunk) * DD;

    const int warp = tid >> 5, lane = tid & 31;
    const int wm = warp & 1, wn = warp >> 1;
    const int lr = lane >> 2, lc = lane & 3;

    // A loader ([k][m]): 2 cp16
    const int ka_r = tid >> 4, ka_c = (tid & 15) * 8;
    // B loader ([k][n]): 4 cp16
    const int kb_r = tid >> 4, kb_c = (tid & 15) * 16;

    const float* Ag = g_K + base + (size_t)ka_r * DD + d0 + ka_c;
    const float* Bg = g_V + base + (size_t)kb_r * DD + kb_c;

    const uint32_t sA = (uint32_t)__cvta_generic_to_shared(As);
    const uint32_t sB = (uint32_t)__cvta_generic_to_shared(Bs);

    float acc[4][8][4] = {};

    #define KV_ISSUE(st, l0) do {                                              \
        const float* _ag = Ag + (size_t)(l0) * DD;                             \
        cp16(sA + ((st)*2176 + ka_r*AKV + ka_c) * 4,     _ag);                 \
        cp16(sA + ((st)*2176 + ka_r*AKV + ka_c + 4) * 4, _ag + 4);             \
        const float* _bg = Bg + (size_t)(l0) * DD;                             \
        cp16(sB + ((st)*4224 + kb_r*BN + kb_c) * 4,      _bg);                 \
        cp16(sB + ((st)*4224 + kb_r*BN + kb_c + 4) * 4,  _bg + 4);             \
        cp16(sB + ((st)*4224 + kb_r*BN + kb_c + 8) * 4,  _bg + 8);             \
        cp16(sB + ((st)*4224 + kb_r*BN + kb_c + 12) * 4, _bg + 12);            \
    } while (0)

    KV_ISSUE(0, 0);  CP_COMMIT();
    KV_ISSUE(1, 16); CP_COMMIT();

    const int NST = lchunk / 16;   // 32
    for (int s = 0; s < NST; s++) {
        const int cur = s & 1;
        if (s + 1 < NST) CP_WAIT1(); else CP_WAIT0();
        __syncthreads();
        const float* a0 = As + cur * 2176;
        const float* bgs = Bs + cur * 4224;
        #pragma unroll
        for (int ks = 0; ks < 2; ks++) {
            const int kb = ks * 8;
            uint32_t af[4][4], bf[8][2];
            #pragma unroll
            for (int mt = 0; mt < 4; mt++) {
                const int m = wm * 64 + mt * 16 + lr;
                af[mt][0] = __float_as_uint(a0[(kb + lc)     * AKV + m]);
                af[mt][1] = __float_as_uint(a0[(kb + lc)     * AKV + m + 8]);
                af[mt][2] = __float_as_uint(a0[(kb + 4 + lc) * AKV + m]);
                af[mt][3] = __float_as_uint(a0[(kb + 4 + lc) * AKV + m + 8]);
            }
            #pragma unroll
            for (int nt = 0; nt < 8; nt++) {
                const int n = wn * 64 + nt * 8 + lr;
                bf[nt][0] = __float_as_uint(bgs[(kb + lc)     * BN + n]);
                bf[nt][1] = __float_as_uint(bgs[(kb + 4 + lc) * BN + n]);
            }
            #pragma unroll
            for (int mt = 0; mt < 4; mt++)
                #pragma unroll
                for (int nt = 0; nt < 8; nt++)
                    mma8(acc[mt][nt], af[mt], bf[nt]);
        }
        __syncthreads();
        if (s + 2 < NST) { KV_ISSUE(cur, (s + 2) * 16); CP_COMMIT(); }
    }
    #undef KV_ISSUE

    float* outp = g_kvpart + (size_t)bz * DD * DD;
    #pragma unroll
    for (int mt = 0; mt < 4; mt++) {
        const int d = d0 + wm * 64 + mt * 16 + lr;
        #pragma unroll
        for (int nt = 0; nt < 8; nt++) {
            const int h = wn * 64 + nt * 8 + 2 * lc;
            float2 p0 = { acc[mt][nt][0], acc[mt][nt][1] };
            float2 p1 = { acc[mt][nt][2], acc[mt][nt][3] };
            *(float2*)&outp[(size_t)d * DD + h]       = p0;
            *(float2*)&outp[(size_t)(d + 8) * DD + h] = p1;
        }
    }
}

// deterministic reduce + round (no transpose; kv natural [d][h] = B[k][n])
__global__ void reduce_kv_kernel()
{
    int i = blockIdx.x * blockDim.x + threadIdx.x;
    if (i >= BB * DD * DD) return;
    int b  = i >> 16;
    int dh = i & 65535;
    float s = 0.0f;
    #pragma unroll
    for (int sp = 0; sp < KVS; sp++)
        s += g_kvpart[(size_t)(b * KVS + sp) * DD * DD + dh];
    g_kv[i] = __uint_as_float(f2tf(s));
}

// ============================================================
// out[row,:] = (Q[row,:] @ kv[b]) / z[row]. Same tiling as proj.
// A = g_Q (pre-rounded, [m][k]), B = g_kv[b] ([k][n]).
// ============================================================
__global__ __launch_bounds__(256)
void out_g(float* __restrict__ out)
{
    extern __shared__ __align__(16) float sm[];
    float* As = sm;
    float* Bs = sm + 5120;

    const int tid  = threadIdx.x;
    const int row0 = blockIdx.x * 128;
    const int bbatch = row0 >> 12;

    const int warp = tid >> 5, lane = tid & 31;
    const int wm = warp & 1, wn = warp >> 1;
    const int lr = lane >> 2, lc = lane & 3;

    const int a_r = tid >> 1, a_k = (tid & 1) * 8;
    const int b_r = tid >> 4, b_c = (tid & 15) * 16;

    const float* Ag = g_Q + (size_t)(row0 + a_r) * DD + a_k;
    const float* Bg = g_kv + (size_t)bbatch * DD * DD + (size_t)b_r * DD + b_c;

    const uint32_t sA = (uint32_t)__cvta_generic_to_shared(As);
    const uint32_t sB = (uint32_t)__cvta_generic_to_shared(Bs);

    float acc[4][8][4] = {};

    #define O_ISSUE(st, k0) do {                                               \
        cp16(sA + ((st)*2560 + a_r*APJ + a_k) * 4,     Ag + (k0));             \
        cp16(sA + ((st)*2560 + a_r*APJ + a_k + 4) * 4, Ag + (k0) + 4);         \
        const float* _bg = Bg + (size_t)(k0) * DD;                             \
        cp16(sB + ((st)*4224 + b_r*BN + b_c) * 4,      _bg);                   \
        cp16(sB + ((st)*4224 + b_r*BN + b_c + 4) * 4,  _bg + 4);               \
        cp16(sB + ((st)*4224 + b_r*BN + b_c + 8) * 4,  _bg + 8);               \
        cp16(sB + ((st)*4224 + b_r*BN + b_c + 12) * 4, _bg + 12);              \
    } while (0)

    O_ISSUE(0, 0);  CP_COMMIT();
    O_ISSUE(1, 16); CP_COMMIT();

    const int NST = DD / 16;
    for (int s = 0; s < NST; s++) {
        const int cur = s & 1;
        if (s + 1 < NST) CP_WAIT1(); else CP_WAIT0();
        __syncthreads();
        const float* a0 = As + cur * 2560;
        const float* bgs = Bs + cur * 4224;
        #pragma unroll
        for (int ks = 0; ks < 2; ks++) {
            const int kb = ks * 8;
            uint32_t af[4][4], bf[8][2];
            #pragma unroll
            for (int mt = 0; mt < 4; mt++) {
                const int m = wm * 64 + mt * 16 + lr;
                af[mt][0] = __float_as_uint(a0[(m)     * APJ + kb + lc]);
                af[mt][1] = __float_as_uint(a0[(m + 8) * APJ + kb + lc]);
                af[mt][2] = __float_as_uint(a0[(m)     * APJ + kb + lc + 4]);
                af[mt][3] = __float_as_uint(a0[(m + 8) * APJ + kb + lc + 4]);
            }
            #pragma unroll
            for (int nt = 0; nt < 8; nt++) {
                const int n = wn * 64 + nt * 8 + lr;
                bf[nt][0] = __float_as_uint(bgs[(kb + lc)     * BN + n]);
                bf[nt][1] = __float_as_uint(bgs[(kb + 4 + lc) * BN + n]);
            }
            #pragma unroll
            for (int mt = 0; mt < 4; mt++)
                #pragma unroll
                for (int nt = 0; nt < 8; nt++)
                    mma8(acc[mt][nt], af[mt], bf[nt]);
        }
        __syncthreads();
        if (s + 2 < NST) { O_ISSUE(cur, (s + 2) * 16); CP_COMMIT(); }
    }
    #undef O_ISSUE

    #pragma unroll
    for (int mt = 0; mt < 4; mt++) {
        const int r0 = row0 + wm * 64 + mt * 16 + lr;
        const float iz0 = 1.0f / g_z[r0];
        const float iz1 = 1.0f / g_z[r0 + 8];
        #pragma unroll
        for (int nt = 0; nt < 8; nt++) {
            const int c = wn * 64 + nt * 8 + 2 * lc;
            float2 p0 = { acc[mt][nt][0] * iz0, acc[mt][nt][1] * iz0 };
            float2 p1 = { acc[mt][nt][2] * iz1, acc[mt][nt][3] * iz1 };
            *(float2*)&out[(size_t)r0 * DD + c]       = p0;
            *(float2*)&out[(size_t)(r0 + 8) * DD + c] = p1;
        }
    }
}

// ============================================================
extern "C" void kernel_launch(void* const* d_in, const int* in_sizes, int n_in,
                              void* d_out, int out_size)
{
    const float* q  = (const float*)d_in[0];
    const float* k  = (const float*)d_in[1];
    const float* v  = (const float*)d_in[2];
    const float* Wq = (const float*)d_in[3];
    const float* bq = (const float*)d_in[4];
    const float* Wk = (const float*)d_in[5];
    const float* bk = (const float*)d_in[6];
    const float* Wv = (const float*)d_in[7];
    const float* bv = (const float*)d_in[8];
    float* out = (float*)d_out;

    const int SMEM_P = 13568 * 4;   // proj/out: 54272 B
    const int SMEM_K = 12800 * 4;   // kv:       51200 B
    static int attr_done = 0;
    if (!attr_done) {
        cudaFuncSetAttribute(proj_g, cudaFuncAttributeMaxDynamicSharedMemorySize, SMEM_P);
        cudaFuncSetAttribute(out_g,  cudaFuncAttributeMaxDynamicSharedMemorySize, SMEM_P);
        cudaFuncSetAttribute(kv_g,   cudaFuncAttributeMaxDynamicSharedMemorySize, SMEM_K);
        attr_done = 1;
    }

    // 0. round weights
    prep_w<<<dim3(256, 3), 256>>>(Wq, Wk, Wv);

    // 1. V + K projections (fused launch; K emits colsum partials)
    proj_g<<<dim3(256, 1, 2), 256, SMEM_P>>>(v, k, q, bv, bk, bq, 0);

    // 2. ksum
    reduce_kcs_kernel<<<(BB * DD + 255) / 256, 256>>>();

    // 3. Q projection (+z, needs ksum)
    proj_g<<<dim3(256, 1, 1), 256, SMEM_P>>>(v, k, q, bv, bk, bq, 1);

    // 4. kv = K^T V (split-K) + deterministic reduce/round
    kv_g<<<dim3(2, BB * KVS), 256, SMEM_K>>>();
    reduce_kv_kernel<<<(BB * DD * DD + 255) / 256, 256>>>();

    // 5. out = (Q @ kv) / z
    out_g<<<256, 256, SMEM_P>>>(out);
}

// round 8
// speedup vs baseline: 1.0549x; 1.0549x over previous
#include <cuda_runtime.h>
#include <math.h>
#include <stdint.h>

#define BB 8
#define LL 4096
#define DD 256
#define ML (BB*LL)          // 32768 rows
#define KVS 8               // split-K for kv (deterministic)

#define AP 20    // proj/out A smem row stride ([m][k]: 16 k + 4 pad)
#define BP 132   // [k][n] smem row stride (128 + 4 pad)

// buffer sizes (floats)
#define ABUF (128*AP)   // 2560
#define BBUF (16*BP)    // 2112

// ---- scratch (device globals; no allocations allowed) ----
__device__ float g_Q[ML*DD];       // tf32-pre-rounded
__device__ float g_K[ML*DD];       // tf32-pre-rounded
__device__ float g_V[ML*DD];       // tf32-pre-rounded
__device__ float g_Wr[3*DD*DD];    // rounded weights [w][k][n] (0=q,1=k,2=v)
__device__ float g_kvpart[KVS*BB*DD*DD];
__device__ float g_kv[BB*DD*DD];   // rounded, natural [d][h]
__device__ float g_kcs[256*DD];    // K colsum partials per 128-row block
__device__ float g_ksum[BB*DD];
__device__ float g_zpart[2*ML];    // z partials per 128-col block

// ---- helpers ----
__device__ __forceinline__ uint32_t f2tf(float x) {
    uint32_t r; asm("cvt.rna.tf32.f32 %0, %1;" : "=r"(r) : "f"(x)); return r;
}
__device__ __forceinline__ void mma8(float* d, const uint32_t* a, const uint32_t* b) {
    asm volatile(
        "mma.sync.aligned.m16n8k8.row.col.f32.tf32.tf32.f32 "
        "{%0,%1,%2,%3}, {%4,%5,%6,%7}, {%8,%9}, {%0,%1,%2,%3};\n"
        : "+f"(d[0]), "+f"(d[1]), "+f"(d[2]), "+f"(d[3])
        : "r"(a[0]), "r"(a[1]), "r"(a[2]), "r"(a[3]), "r"(b[0]), "r"(b[1]));
}
__device__ __forceinline__ void cp16(uint32_t saddr, const void* g) {
    asm volatile("cp.async.cg.shared.global [%0], [%1], 16;\n"
                 :: "r"(saddr), "l"(g) : "memory");
}
#define CP_COMMIT() asm volatile("cp.async.commit_group;\n" ::: "memory")
#define CP_WAIT1()  asm volatile("cp.async.wait_group 1;\n" ::: "memory")
#define CP_WAIT0()  asm volatile("cp.async.wait_group 0;\n" ::: "memory")

__device__ __forceinline__ void mma_sweep(float acc[4][4][4],
                                          const uint32_t af[4][4],
                                          const uint32_t bf[4][2]) {
    #pragma unroll
    for (int mt = 0; mt < 4; mt++)
        #pragma unroll
        for (int nt = 0; nt < 4; nt++)
            mma8(acc[mt][nt], af[mt], bf[nt]);
}

// ============================================================
// Weight pre-round: g_Wr[w][k][n] = round(W_w[k][n])
// ============================================================
__global__ void prep_w(const float* __restrict__ Wq, const float* __restrict__ Wk,
                       const float* __restrict__ Wv)
{
    const int kk = blockIdx.x, w = blockIdx.y, n = threadIdx.x;
    const float* W = (w == 0) ? Wq : (w == 1) ? Wk : Wv;
    g_Wr[(size_t)w * DD * DD + (size_t)kk * DD + n] =
        __uint_as_float(f2tf(W[(size_t)kk * DD + n]));
}

// ============================================================
// Projection: Y = act(X @ W + bias), rounded store.
// CTA 128x128, warp 64x32 (2m x 4n), BK=16, 3-stage cp.async ring,
// ONE barrier per stage. B pre-rounded (no cvt); A cvt at frag load.
// MODE 0: plain (V). MODE 1: +colsum (K). MODE 2: +z (Q).
// ============================================================
template<int ACT, int MODE>
__global__ __launch_bounds__(256)
void proj_mma(const float* __restrict__ X, const float* __restrict__ W,
              const float* __restrict__ bias, float* __restrict__ Y)
{
    extern __shared__ __align__(16) float sm[];
    float* As = sm;                 // 3 * ABUF
    float* Bs = sm + 3 * ABUF;      // 3 * BBUF
    float* scr = sm;                // epilogue staging (aliases As; post-sync)

    const int tid  = threadIdx.x;
    const int row0 = blockIdx.y * 128;
    const int col0 = blockIdx.x * 128;

    const int warp = tid >> 5, lane = tid & 31;
    const int wm = warp & 1, wn = warp >> 1;
    const int lr = lane >> 2, lc = lane & 3;

    const int a_r   = (2 * tid) >> 2;          // 0..127
    const int a_off = ((2 * tid) & 3) * 4;     // {0,8}
    const int b_r   = (2 * tid) >> 5;          // 0..15
    const int b_off = ((2 * tid) & 31) * 4;    // {0,8,...,120}

    const float* Ag = X + (size_t)(row0 + a_r) * DD + a_off;
    const float* Bg = W + (size_t)b_r * DD + col0 + b_off;

    const uint32_t sA = (uint32_t)__cvta_generic_to_shared(As);
    const uint32_t sB = (uint32_t)__cvta_generic_to_shared(Bs);

    float acc[4][4][4] = {};

    #define P_ISSUE(st, k0) do {                                               \
        cp16(sA + ((st)*ABUF + a_r*AP + a_off) * 4,     Ag + (k0));            \
        cp16(sA + ((st)*ABUF + a_r*AP + a_off + 4) * 4, Ag + (k0) + 4);        \
        cp16(sB + ((st)*BBUF + b_r*BP + b_off) * 4,     Bg + (size_t)(k0)*DD); \
        cp16(sB + ((st)*BBUF + b_r*BP + b_off + 4) * 4, Bg + (size_t)(k0)*DD + 4); \
    } while (0)

    #define P_LDFRAG(af, bf, st, kb) do {                                      \
        const float* _a = As + (st) * ABUF;                                    \
        const float* _b = Bs + (st) * BBUF;                                    \
        _Pragma("unroll")                                                      \
        for (int mt = 0; mt < 4; mt++) {                                       \
            const int m = wm * 64 + mt * 16 + lr;                              \
            af[mt][0] = f2tf(_a[(m)   * AP + (kb) + lc]);                      \
            af[mt][1] = f2tf(_a[(m+8) * AP + (kb) + lc]);                      \
            af[mt][2] = f2tf(_a[(m)   * AP + (kb) + lc + 4]);                  \
            af[mt][3] = f2tf(_a[(m+8) * AP + (kb) + lc + 4]);                  \
        }                                                                      \
        _Pragma("unroll")                                                      \
        for (int nt = 0; nt < 4; nt++) {                                       \
            const int n = wn * 32 + nt * 8 + lr;                               \
            bf[nt][0] = __float_as_uint(_b[((kb) + lc)     * BP + n]);         \
            bf[nt][1] = __float_as_uint(_b[((kb) + 4 + lc) * BP + n]);         \
        }                                                                      \
    } while (0)

    P_ISSUE(0, 0);  CP_COMMIT();
    P_ISSUE(1, 16); CP_COMMIT();

    uint32_t af0[4][4], bf0[4][2], af1[4][4], bf1[4][2];
    const int NST = DD / 16;   // 16
    int put = 2, get = 0;
    for (int s = 0; s < NST; s++) {
        if (s + 1 < NST) CP_WAIT1(); else CP_WAIT0();
        __syncthreads();
        if (s + 2 < NST) {
            P_ISSUE(put, (s + 2) * 16); CP_COMMIT();
            if (++put == 3) put = 0;
        }
        P_LDFRAG(af0, bf0, get, 0);
        P_LDFRAG(af1, bf1, get, 8);
        if (++get == 3) get = 0;
        mma_sweep(acc, af0, bf0);
        mma_sweep(acc, af1, bf1);
    }
    #undef P_ISSUE
    #undef P_LDFRAG
    __syncthreads();   // before scr aliasing / epilogue staging

    // ---- epilogue ----
    const int bbatch = row0 >> 12;
    float cs[4][2], za[4][2], ksv[4][2];
    if (MODE == 1) {
        #pragma unroll
        for (int nt = 0; nt < 4; nt++) { cs[nt][0] = 0.f; cs[nt][1] = 0.f; }
    }
    if (MODE == 2) {
        #pragma unroll
        for (int mt = 0; mt < 4; mt++) { za[mt][0] = 0.f; za[mt][1] = 0.f; }
        #pragma unroll
        for (int nt = 0; nt < 4; nt++) {
            const int c = col0 + wn * 32 + nt * 8 + 2 * lc;
            ksv[nt][0] = g_ksum[bbatch * DD + c];
            ksv[nt][1] = g_ksum[bbatch * DD + c + 1];
        }
    }

    #pragma unroll
    for (int mt = 0; mt < 4; mt++) {
        const int r0 = row0 + wm * 64 + mt * 16 + lr;
        #pragma unroll
        for (int nt = 0; nt < 4; nt++) {
            const int c = col0 + wn * 32 + nt * 8 + 2 * lc;
            const float b0 = bias[c], b1 = bias[c + 1];
            float v0 = acc[mt][nt][0] + b0;
            float v1 = acc[mt][nt][1] + b1;
            float v2 = acc[mt][nt][2] + b0;
            float v3 = acc[mt][nt][3] + b1;
            if (ACT) {
                v0 = (v0 > 0.0f) ? (v0 + 1.0f) : __expf(v0);
                v1 = (v1 > 0.0f) ? (v1 + 1.0f) : __expf(v1);
                v2 = (v2 > 0.0f) ? (v2 + 1.0f) : __expf(v2);
                v3 = (v3 > 0.0f) ? (v3 + 1.0f) : __expf(v3);
            }
            if (MODE == 1) {
                cs[nt][0] += v0 + v2;
                cs[nt][1] += v1 + v3;
            }
            if (MODE == 2) {
                za[mt][0] = fmaf(v0, ksv[nt][0], fmaf(v1, ksv[nt][1], za[mt][0]));
                za[mt][1] = fmaf(v2, ksv[nt][0], fmaf(v3, ksv[nt][1], za[mt][1]));
            }
            float2 p0 = { __uint_as_float(f2tf(v0)), __uint_as_float(f2tf(v1)) };
            float2 p1 = { __uint_as_float(f2tf(v2)), __uint_as_float(f2tf(v3)) };
            *(float2*)&Y[(size_t)r0 * DD + c]       = p0;
            *(float2*)&Y[(size_t)(r0 + 8) * DD + c] = p1;
        }
    }

    if (MODE == 1) {
        #pragma unroll
        for (int nt = 0; nt < 4; nt++) {
            #pragma unroll
            for (int off = 4; off < 32; off <<= 1) {
                cs[nt][0] += __shfl_xor_sync(0xffffffffu, cs[nt][0], off);
                cs[nt][1] += __shfl_xor_sync(0xffffffffu, cs[nt][1], off);
            }
        }
        if (lr == 0) {
            #pragma unroll
            for (int nt = 0; nt < 4; nt++) {
                const int cl = wn * 32 + nt * 8 + 2 * lc;
                scr[wm * 128 + cl]     = cs[nt][0];
                scr[wm * 128 + cl + 1] = cs[nt][1];
            }
        }
        __syncthreads();
        if (tid < 128)
            g_kcs[(size_t)blockIdx.y * DD + col0 + tid] = scr[tid] + scr[128 + tid];
    }
    if (MODE == 2) {
        #pragma unroll
        for (int mt = 0; mt < 4; mt++) {
            #pragma unroll
            for (int off = 1; off < 4; off <<= 1) {
                za[mt][0] += __shfl_xor_sync(0xffffffffu, za[mt][0], off);
                za[mt][1] += __shfl_xor_sync(0xffffffffu, za[mt][1], off);
            }
        }
        if (lc == 0) {
            #pragma unroll
            for (int mt = 0; mt < 4; mt++) {
                const int rl = wm * 64 + mt * 16 + lr;
                scr[wn * 128 + rl]     = za[mt][0];
                scr[wn * 128 + rl + 8] = za[mt][1];
            }
        }
        __syncthreads();
        if (tid < 128)
            g_zpart[(size_t)blockIdx.x * ML + row0 + tid] =
                scr[tid] + scr[128 + tid] + scr[256 + tid] + scr[384 + tid];
    }
}

// ksum[b,d] = sum over 32 row-blocks of g_kcs
__global__ void reduce_kcs_kernel()
{
    int i = blockIdx.x * blockDim.x + threadIdx.x;
    if (i >= BB * DD) return;
    int b = i / DD, d = i % DD;
    float s = 0.0f;
    #pragma unroll
    for (int j = 0; j < 32; j++)
        s += g_kcs[(size_t)(b * 32 + j) * DD + d];
    g_ksum[i] = s;
}

// ============================================================
// kv split-K: kvpart[bz][d,h] = sum_{l in chunk} K[l,d]*V[l,h]
// Both operands [k(l)][feat] natural, pre-rounded (no cvt).
// 3-stage ring, one barrier/stage. grid = (2, 2, BB*KVS)
// ============================================================
__global__ __launch_bounds__(256)
void kv_mma()
{
    extern __shared__ __align__(16) float sm[];
    float* As = sm;                 // 3 * BBUF  ([l][d])
    float* Bs = sm + 3 * BBUF;      // 3 * BBUF  ([l][h])

    const int tid = threadIdx.x;
    const int h0 = blockIdx.x * 128;
    const int d0 = blockIdx.y * 128;
    const int bz = blockIdx.z;
    const int b  = bz / KVS;
    const int sp = bz % KVS;
    const int lchunk = LL / KVS;      // 512
    const size_t base = ((size_t)b * LL + (size_t)sp * lchunk) * DD;

    const int warp = tid >> 5, lane = tid & 31;
    const int wm = warp & 1, wn = warp >> 1;
    const int lr = lane >> 2, lc = lane & 3;

    const int k_r   = (2 * tid) >> 5;
    const int k_off = ((2 * tid) & 31) * 4;

    const float* Ag = g_K + base + (size_t)k_r * DD + d0 + k_off;
    const float* Bg = g_V + base + (size_t)k_r * DD + h0 + k_off;

    const uint32_t sA = (uint32_t)__cvta_generic_to_shared(As);
    const uint32_t sB = (uint32_t)__cvta_generic_to_shared(Bs);

    float acc[4][4][4] = {};

    #define KV_ISSUE(st, l0) do {                                              \
        cp16(sA + ((st)*BBUF + k_r*BP + k_off) * 4,     Ag + (size_t)(l0)*DD);      \
        cp16(sA + ((st)*BBUF + k_r*BP + k_off + 4) * 4, Ag + (size_t)(l0)*DD + 4);  \
        cp16(sB + ((st)*BBUF + k_r*BP + k_off) * 4,     Bg + (size_t)(l0)*DD);      \
        cp16(sB + ((st)*BBUF + k_r*BP + k_off + 4) * 4, Bg + (size_t)(l0)*DD + 4);  \
    } while (0)

    #define KV_LDFRAG(af, bf, st, kb) do {                                     \
        const float* _a = As + (st) * BBUF;                                    \
        const float* _b = Bs + (st) * BBUF;                                    \
        _Pragma("unroll")                                                      \
        for (int mt = 0; mt < 4; mt++) {                                       \
            const int m = wm * 64 + mt * 16 + lr;                              \
            af[mt][0] = __float_as_uint(_a[((kb) + lc)     * BP + m]);         \
            af[mt][1] = __float_as_uint(_a[((kb) + lc)     * BP + m + 8]);     \
            af[mt][2] = __float_as_uint(_a[((kb) + 4 + lc) * BP + m]);         \
            af[mt][3] = __float_as_uint(_a[((kb) + 4 + lc) * BP + m + 8]);     \
        }                                                                      \
        _Pragma("unroll")                                                      \
        for (int nt = 0; nt < 4; nt++) {                                       \
            const int n = wn * 32 + nt * 8 + lr;                               \
            bf[nt][0] = __float_as_uint(_b[((kb) + lc)     * BP + n]);         \
            bf[nt][1] = __float_as_uint(_b[((kb) + 4 + lc) * BP + n]);         \
        }                                                                      \
    } while (0)

    KV_ISSUE(0, 0);  CP_COMMIT();
    KV_ISSUE(1, 16); CP_COMMIT();

    uint32_t af0[4][4], bf0[4][2], af1[4][4], bf1[4][2];
    const int NST = lchunk / 16;   // 32
    int put = 2, get = 0;
    for (int s = 0; s < NST; s++) {
        if (s + 1 < NST) CP_WAIT1(); else CP_WAIT0();
        __syncthreads();
        if (s + 2 < NST) {
            KV_ISSUE(put, (s + 2) * 16); CP_COMMIT();
            if (++put == 3) put = 0;
        }
        KV_LDFRAG(af0, bf0, get, 0);
        KV_LDFRAG(af1, bf1, get, 8);
        if (++get == 3) get = 0;
        mma_sweep(acc, af0, bf0);
        mma_sweep(acc, af1, bf1);
    }
    #undef KV_ISSUE
    #undef KV_LDFRAG

    float* outp = g_kvpart + (size_t)bz * DD * DD;
    #pragma unroll
    for (int mt = 0; mt < 4; mt++) {
        const int d = d0 + wm * 64 + mt * 16 + lr;
        #pragma unroll
        for (int nt = 0; nt < 4; nt++) {
            const int h = h0 + wn * 32 + nt * 8 + 2 * lc;
            float2 p0 = { acc[mt][nt][0], acc[mt][nt][1] };
            float2 p1 = { acc[mt][nt][2], acc[mt][nt][3] };
            *(float2*)&outp[(size_t)d * DD + h]       = p0;
            *(float2*)&outp[(size_t)(d + 8) * DD + h] = p1;
        }
    }
}

// deterministic reduce + round (natural [d][h])
__global__ void reduce_kv_kernel()
{
    int i = blockIdx.x * blockDim.x + threadIdx.x;
    if (i >= BB * DD * DD) return;
    int b  = i >> 16;
    int dh = i & 65535;
    float s = 0.0f;
    #pragma unroll
    for (int sp = 0; sp < KVS; sp++)
        s += g_kvpart[(size_t)(b * KVS + sp) * DD * DD + dh];
    g_kv[i] = __uint_as_float(f2tf(s));
}

// ============================================================
// out[row,:] = (Q[row,:] @ kv[b]) / z[row]; pre-rounded inputs.
// ============================================================
__global__ __launch_bounds__(256)
void out_mma(float* __restrict__ out)
{
    extern __shared__ __align__(16) float sm[];
    float* As = sm;
    float* Bs = sm + 3 * ABUF;

    const int tid  = threadIdx.x;
    const int row0 = blockIdx.y * 128;
    const int col0 = blockIdx.x * 128;
    const int b    = row0 / LL;

    const int warp = tid >> 5, lane = tid & 31;
    const int wm = warp & 1, wn = warp >> 1;
    const int lr = lane >> 2, lc = lane & 3;

    const int a_r   = (2 * tid) >> 2;
    const int a_off = ((2 * tid) & 3) * 4;
    const int b_r   = (2 * tid) >> 5;
    const int b_off = ((2 * tid) & 31) * 4;

    const float* Ag = g_Q + (size_t)(row0 + a_r) * DD + a_off;
    const float* Bg = g_kv + (size_t)b * DD * DD + (size_t)b_r * DD + col0 + b_off;

    const uint32_t sA = (uint32_t)__cvta_generic_to_shared(As);
    const uint32_t sB = (uint32_t)__cvta_generic_to_shared(Bs);

    float acc[4][4][4] = {};

    #define O_ISSUE(st, k0) do {                                               \
        cp16(sA + ((st)*ABUF + a_r*AP + a_off) * 4,     Ag + (k0));            \
        cp16(sA + ((st)*ABUF + a_r*AP + a_off + 4) * 4, Ag + (k0) + 4);        \
        cp16(sB + ((st)*BBUF + b_r*BP + b_off) * 4,     Bg + (size_t)(k0)*DD); \
        cp16(sB + ((st)*BBUF + b_r*BP + b_off + 4) * 4, Bg + (size_t)(k0)*DD + 4); \
    } while (0)

    #define O_LDFRAG(af, bf, st, kb) do {                                      \
        const float* _a = As + (st) * ABUF;                                    \
        const float* _b = Bs + (st) * BBUF;                                    \
        _Pragma("unroll")                                                      \
        for (int mt = 0; mt < 4; mt++) {                                       \
            const int m = wm * 64 + mt * 16 + lr;                              \
            af[mt][0] = __float_as_uint(_a[(m)   * AP + (kb) + lc]);           \
            af[mt][1] = __float_as_uint(_a[(m+8) * AP + (kb) + lc]);           \
            af[mt][2] = __float_as_uint(_a[(m)   * AP + (kb) + lc + 4]);       \
            af[mt][3] = __float_as_uint(_a[(m+8) * AP + (kb) + lc + 4]);       \
        }                                                                      \
        _Pragma("unroll")                                                      \
        for (int nt = 0; nt < 4; nt++) {                                       \
            const int n = wn * 32 + nt * 8 + lr;                               \
            bf[nt][0] = __float_as_uint(_b[((kb) + lc)     * BP + n]);         \
            bf[nt][1] = __float_as_uint(_b[((kb) + 4 + lc) * BP + n]);         \
        }                                                                      \
    } while (0)

    O_ISSUE(0, 0);  CP_COMMIT();
    O_ISSUE(1, 16); CP_COMMIT();

    uint32_t af0[4][4], bf0[4][2], af1[4][4], bf1[4][2];
    const int NST = DD / 16;
    int put = 2, get = 0;
    for (int s = 0; s < NST; s++) {
        if (s + 1 < NST) CP_WAIT1(); else CP_WAIT0();
        __syncthreads();
        if (s + 2 < NST) {
            O_ISSUE(put, (s + 2) * 16); CP_COMMIT();
            if (++put == 3) put = 0;
        }
        O_LDFRAG(af0, bf0, get, 0);
        O_LDFRAG(af1, bf1, get, 8);
        if (++get == 3) get = 0;
        mma_sweep(acc, af0, bf0);
        mma_sweep(acc, af1, bf1);
    }
    #undef O_ISSUE
    #undef O_LDFRAG

    #pragma unroll
    for (int mt = 0; mt < 4; mt++) {
        const int r0 = row0 + wm * 64 + mt * 16 + lr;
        const float iz0 = 1.0f / (g_zpart[r0]     + g_zpart[ML + r0]     + 1e-6f);
        const float iz1 = 1.0f / (g_zpart[r0 + 8] + g_zpart[ML + r0 + 8] + 1e-6f);
        #pragma unroll
        for (int nt = 0; nt < 4; nt++) {
            const int c = col0 + wn * 32 + nt * 8 + 2 * lc;
            float2 p0 = { acc[mt][nt][0] * iz0, acc[mt][nt][1] * iz0 };
            float2 p1 = { acc[mt][nt][2] * iz1, acc[mt][nt][3] * iz1 };
            *(float2*)&out[(size_t)r0 * DD + c]       = p0;
            *(float2*)&out[(size_t)(r0 + 8) * DD + c] = p1;
        }
    }
}

// ============================================================
extern "C" void kernel_launch(void* const* d_in, const int* in_sizes, int n_in,
                              void* d_out, int out_size)
{
    const float* q  = (const float*)d_in[0];
    const float* k  = (const float*)d_in[1];
    const float* v  = (const float*)d_in[2];
    const float* Wq = (const float*)d_in[3];
    const float* bq = (const float*)d_in[4];
    const float* Wk = (const float*)d_in[5];
    const float* bk = (const float*)d_in[6];
    const float* Wv = (const float*)d_in[7];
    const float* bv = (const float*)d_in[8];
    float* out = (float*)d_out;

    float *dQ, *dK, *dV, *dWr;
    cudaGetSymbolAddress((void**)&dQ, g_Q);
    cudaGetSymbolAddress((void**)&dK, g_K);
    cudaGetSymbolAddress((void**)&dV, g_V);
    cudaGetSymbolAddress((void**)&dWr, g_Wr);

    const int SMEM_PO = (3 * ABUF + 3 * BBUF) * 4;   // 56064 B
    const int SMEM_KV = (6 * BBUF) * 4;              // 50688 B
    static int attr_done = 0;
    if (!attr_done) {
        cudaFuncSetAttribute(proj_mma<0,0>, cudaFuncAttributeMaxDynamicSharedMemorySize, SMEM_PO);
        cudaFuncSetAttribute(proj_mma<1,1>, cudaFuncAttributeMaxDynamicSharedMemorySize, SMEM_PO);
        cudaFuncSetAttribute(proj_mma<1,2>, cudaFuncAttributeMaxDynamicSharedMemorySize, SMEM_PO);
        cudaFuncSetAttribute(out_mma,       cudaFuncAttributeMaxDynamicSharedMemorySize, SMEM_PO);
        cudaFuncSetAttribute(kv_mma,        cudaFuncAttributeMaxDynamicSharedMemorySize, SMEM_KV);
        attr_done = 1;
    }

    // 0. round weights once
    prep_w<<<dim3(256, 3), 256>>>(Wq, Wk, Wv);

    dim3 gProj(DD / 128, ML / 128);

    // 1-2. V (plain), K (+colsum partials)
    proj_mma<0,0><<<gProj, 256, SMEM_PO>>>(v, dWr + 2 * DD * DD, bv, dV);
    proj_mma<1,1><<<gProj, 256, SMEM_PO>>>(k, dWr + 1 * DD * DD, bk, dK);

    // 3. ksum
    reduce_kcs_kernel<<<(BB * DD + 255) / 256, 256>>>();

    // 4. Q (+z partials)
    proj_mma<1,2><<<gProj, 256, SMEM_PO>>>(q, dWr, bq, dQ);

    // 5. kv = K^T V (split-K) + deterministic reduce/round
    dim3 gKV(DD / 128, DD / 128, BB * KVS);
    kv_mma<<<gKV, 256, SMEM_KV>>>();
    reduce_kv_kernel<<<(BB * DD * DD + 255) / 256, 256>>>();

    // 6. out = (Q @ kv) / z
    dim3 gOut(DD / 128, ML / 128);
    out_mma<<<gOut, 256, SMEM_PO>>>(out);
}

// round 9
// speedup vs baseline: 1.1756x; 1.1144x over previous
#include <cuda_runtime.h>
#include <math.h>
#include <stdint.h>

#define BB 8
#define LL 4096
#define DD 256
#define ML (BB*LL)          // 32768 rows
#define KVS 8               // split-K for kv (deterministic)

#define AP 20    // proj/out A smem row stride ([m][k]: 16 k + 4 pad)
#define BP 136   // [k][n] smem row stride (128 + 8 pad) -> conflict-free frags

// ---- scratch (device globals; no allocations allowed) ----
__device__ float g_Q[ML*DD];       // tf32-pre-rounded
__device__ float g_K[ML*DD];       // tf32-pre-rounded
__device__ float g_V[ML*DD];       // tf32-pre-rounded
__device__ float g_Wr[3*DD*DD];    // rounded weights [w][k][n] (0=q,1=k,2=v)
__device__ float g_kvpart[KVS*BB*DD*DD];
__device__ float g_kv[BB*DD*DD];   // rounded, natural [d][h]
__device__ float g_kcs[256*DD];    // K colsum partials per 128-row block
__device__ float g_ksum[BB*DD];
__device__ float g_zpart[2*ML];    // z partials per 128-col block

// ---- helpers ----
__device__ __forceinline__ uint32_t f2tf(float x) {
    uint32_t r; asm("cvt.rna.tf32.f32 %0, %1;" : "=r"(r) : "f"(x)); return r;
}
__device__ __forceinline__ void mma8(float* d, const uint32_t* a, const uint32_t* b) {
    asm volatile(
        "mma.sync.aligned.m16n8k8.row.col.f32.tf32.tf32.f32 "
        "{%0,%1,%2,%3}, {%4,%5,%6,%7}, {%8,%9}, {%0,%1,%2,%3};\n"
        : "+f"(d[0]), "+f"(d[1]), "+f"(d[2]), "+f"(d[3])
        : "r"(a[0]), "r"(a[1]), "r"(a[2]), "r"(a[3]), "r"(b[0]), "r"(b[1]));
}
__device__ __forceinline__ void cp16(uint32_t saddr, const void* g) {
    asm volatile("cp.async.cg.shared.global [%0], [%1], 16;\n"
                 :: "r"(saddr), "l"(g) : "memory");
}
#define CP_COMMIT() asm volatile("cp.async.commit_group;\n" ::: "memory")
#define CP_WAIT1()  asm volatile("cp.async.wait_group 1;\n" ::: "memory")
#define CP_WAIT0()  asm volatile("cp.async.wait_group 0;\n" ::: "memory")

__device__ __forceinline__ void mma_sweep(float acc[4][4][4],
                                          const uint32_t af[4][4],
                                          const uint32_t bf[4][2]) {
    #pragma unroll
    for (int mt = 0; mt < 4; mt++)
        #pragma unroll
        for (int nt = 0; nt < 4; nt++)
            mma8(acc[mt][nt], af[mt], bf[nt]);
}

// ============================================================
// Weight pre-round: g_Wr[w][k][n] = round(W_w[k][n])
// ============================================================
__global__ void prep_w(const float* __restrict__ Wq, const float* __restrict__ Wk,
                       const float* __restrict__ Wv)
{
    const int kk = blockIdx.x, w = blockIdx.y, n = threadIdx.x;
    const float* W = (w == 0) ? Wq : (w == 1) ? Wk : Wv;
    g_Wr[(size_t)w * DD * DD + (size_t)kk * DD + n] =
        __uint_as_float(f2tf(W[(size_t)kk * DD + n]));
}

// ============================================================
// Projection: Y = act(X @ W + bias), rounded store. R5 loop structure.
// MODE 0: plain (V). MODE 1: +colsum (K). MODE 2: +z (Q).
// ============================================================
template<int ACT, int MODE>
__global__ __launch_bounds__(256)
void proj_mma(const float* __restrict__ X, const float* __restrict__ W,
              const float* __restrict__ bias, float* __restrict__ Y)
{
    __shared__ __align__(16) float As[2][128*AP];   // [m][k]
    __shared__ __align__(16) float Bs[2][16*BP];    // [k][n], pre-rounded
    __shared__ float red_s[4][128];                 // fused-reduction staging

    const int tid  = threadIdx.x;
    const int row0 = blockIdx.y * 128;
    const int col0 = blockIdx.x * 128;

    const int warp = tid >> 5, lane = tid & 31;
    const int wm = warp & 1, wn = warp >> 1;
    const int lr = lane >> 2, lc = lane & 3;

    const int a_r   = (2 * tid) >> 2;
    const int a_off = ((2 * tid) & 3) * 4;
    const int b_r   = (2 * tid) >> 5;
    const int b_off = ((2 * tid) & 31) * 4;

    const float* Ag = X + (size_t)(row0 + a_r) * DD + a_off;
    const float* Bg = W + (size_t)b_r * DD + col0 + b_off;

    const uint32_t sA = (uint32_t)__cvta_generic_to_shared(&As[0][0]);
    const uint32_t sB = (uint32_t)__cvta_generic_to_shared(&Bs[0][0]);

    float acc[4][4][4] = {};

    #define P_ISSUE(st, k0) do {                                               \
        cp16(sA + ((st)*128*AP + a_r*AP + a_off) * 4,     Ag + (k0));          \
        cp16(sA + ((st)*128*AP + a_r*AP + a_off + 4) * 4, Ag + (k0) + 4);      \
        cp16(sB + ((st)*16*BP + b_r*BP + b_off) * 4,      Bg + (size_t)(k0)*DD);     \
        cp16(sB + ((st)*16*BP + b_r*BP + b_off + 4) * 4,  Bg + (size_t)(k0)*DD + 4); \
    } while (0)

    #define P_LDFRAG(af, bf, st, kb) do {                                      \
        _Pragma("unroll")                                                      \
        for (int mt = 0; mt < 4; mt++) {                                       \
            const int m = wm * 64 + mt * 16 + lr;                              \
            af[mt][0] = f2tf(As[st][(m)   * AP + (kb) + lc]);                  \
            af[mt][1] = f2tf(As[st][(m+8) * AP + (kb) + lc]);                  \
            af[mt][2] = f2tf(As[st][(m)   * AP + (kb) + lc + 4]);              \
            af[mt][3] = f2tf(As[st][(m+8) * AP + (kb) + lc + 4]);              \
        }                                                                      \
        _Pragma("unroll")                                                      \
        for (int nt = 0; nt < 4; nt++) {                                       \
            const int n = wn * 32 + nt * 8 + lr;                               \
            bf[nt][0] = __float_as_uint(Bs[st][((kb) + lc)     * BP + n]);     \
            bf[nt][1] = __float_as_uint(Bs[st][((kb) + 4 + lc) * BP + n]);     \
        }                                                                      \
    } while (0)

    P_ISSUE(0, 0);  CP_COMMIT();
    P_ISSUE(1, 16); CP_COMMIT();
    CP_WAIT1();
    __syncthreads();

    uint32_t af0[4][4], bf0[4][2], af1[4][4], bf1[4][2];
    P_LDFRAG(af0, bf0, 0, 0);

    const int NST = DD / 16;   // 16
    for (int s = 0; s < NST; s++) {
        const int cur = s & 1;
        P_LDFRAG(af1, bf1, cur, 8);
        mma_sweep(acc, af0, bf0);
        __syncthreads();
        if (s + 2 < NST) { P_ISSUE(cur, (s + 2) * 16); CP_COMMIT(); }
        mma_sweep(acc, af1, bf1);
        if (s + 1 < NST) {
            if (s + 2 < NST) CP_WAIT1(); else CP_WAIT0();
            __syncthreads();
            P_LDFRAG(af0, bf0, cur ^ 1, 0);
        }
    }
    #undef P_ISSUE
    #undef P_LDFRAG

    // ---- epilogue ----
    const int bbatch = row0 >> 12;
    float cs[4][2], za[4][2], ksv[4][2];
    if (MODE == 1) {
        #pragma unroll
        for (int nt = 0; nt < 4; nt++) { cs[nt][0] = 0.f; cs[nt][1] = 0.f; }
    }
    if (MODE == 2) {
        #pragma unroll
        for (int mt = 0; mt < 4; mt++) { za[mt][0] = 0.f; za[mt][1] = 0.f; }
        #pragma unroll
        for (int nt = 0; nt < 4; nt++) {
            const int c = col0 + wn * 32 + nt * 8 + 2 * lc;
            ksv[nt][0] = g_ksum[bbatch * DD + c];
            ksv[nt][1] = g_ksum[bbatch * DD + c + 1];
        }
    }

    #pragma unroll
    for (int mt = 0; mt < 4; mt++) {
        const int r0 = row0 + wm * 64 + mt * 16 + lr;
        #pragma unroll
        for (int nt = 0; nt < 4; nt++) {
            const int c = col0 + wn * 32 + nt * 8 + 2 * lc;
            const float b0 = bias[c], b1 = bias[c + 1];
            float v0 = acc[mt][nt][0] + b0;
            float v1 = acc[mt][nt][1] + b1;
            float v2 = acc[mt][nt][2] + b0;
            float v3 = acc[mt][nt][3] + b1;
            if (ACT) {
                v0 = (v0 > 0.0f) ? (v0 + 1.0f) : __expf(v0);
                v1 = (v1 > 0.0f) ? (v1 + 1.0f) : __expf(v1);
                v2 = (v2 > 0.0f) ? (v2 + 1.0f) : __expf(v2);
                v3 = (v3 > 0.0f) ? (v3 + 1.0f) : __expf(v3);
            }
            if (MODE == 1) {
                cs[nt][0] += v0 + v2;
                cs[nt][1] += v1 + v3;
            }
            if (MODE == 2) {
                za[mt][0] = fmaf(v0, ksv[nt][0], fmaf(v1, ksv[nt][1], za[mt][0]));
                za[mt][1] = fmaf(v2, ksv[nt][0], fmaf(v3, ksv[nt][1], za[mt][1]));
            }
            float2 p0 = { __uint_as_float(f2tf(v0)), __uint_as_float(f2tf(v1)) };
            float2 p1 = { __uint_as_float(f2tf(v2)), __uint_as_float(f2tf(v3)) };
            *(float2*)&Y[(size_t)r0 * DD + c]       = p0;
            *(float2*)&Y[(size_t)(r0 + 8) * DD + c] = p1;
        }
    }

    if (MODE == 1) {
        #pragma unroll
        for (int nt = 0; nt < 4; nt++) {
            #pragma unroll
            for (int off = 4; off < 32; off <<= 1) {
                cs[nt][0] += __shfl_xor_sync(0xffffffffu, cs[nt][0], off);
                cs[nt][1] += __shfl_xor_sync(0xffffffffu, cs[nt][1], off);
            }
        }
        if (lr == 0) {
            #pragma unroll
            for (int nt = 0; nt < 4; nt++) {
                const int cl = wn * 32 + nt * 8 + 2 * lc;
                red_s[wm][cl]     = cs[nt][0];
                red_s[wm][cl + 1] = cs[nt][1];
            }
        }
        __syncthreads();
        if (tid < 128)
            g_kcs[(size_t)blockIdx.y * DD + col0 + tid] = red_s[0][tid] + red_s[1][tid];
    }
    if (MODE == 2) {
        #pragma unroll
        for (int mt = 0; mt < 4; mt++) {
            #pragma unroll
            for (int off = 1; off < 4; off <<= 1) {
                za[mt][0] += __shfl_xor_sync(0xffffffffu, za[mt][0], off);
                za[mt][1] += __shfl_xor_sync(0xffffffffu, za[mt][1], off);
            }
        }
        if (lc == 0) {
            #pragma unroll
            for (int mt = 0; mt < 4; mt++) {
                const int rl = wm * 64 + mt * 16 + lr;
                red_s[wn][rl]     = za[mt][0];
                red_s[wn][rl + 8] = za[mt][1];
            }
        }
        __syncthreads();
        if (tid < 128)
            g_zpart[(size_t)blockIdx.x * ML + row0 + tid] =
                red_s[0][tid] + red_s[1][tid] + red_s[2][tid] + red_s[3][tid];
    }
}

// ksum[b,d] = sum over 32 row-blocks of g_kcs
__global__ void reduce_kcs_kernel()
{
    int i = blockIdx.x * blockDim.x + threadIdx.x;
    if (i >= BB * DD) return;
    int b = i / DD, d = i % DD;
    float s = 0.0f;
    #pragma unroll
    for (int j = 0; j < 32; j++)
        s += g_kcs[(size_t)(b * 32 + j) * DD + d];
    g_ksum[i] = s;
}

// ============================================================
// kv split-K: kvpart[bz][d,h] = sum_{l in chunk} K[l,d]*V[l,h]
// pre-rounded inputs (no cvt); BP=136 conflict-free frags.
// ============================================================
__global__ __launch_bounds__(256)
void kv_mma()
{
    __shared__ __align__(16) float As[2][16*BP];   // [l][d]
    __shared__ __align__(16) float Bs[2][16*BP];   // [l][h]

    const int tid = threadIdx.x;
    const int h0 = blockIdx.x * 128;
    const int d0 = blockIdx.y * 128;
    const int bz = blockIdx.z;
    const int b  = bz / KVS;
    const int sp = bz % KVS;
    const int lchunk = LL / KVS;      // 512
    const size_t base = ((size_t)b * LL + (size_t)sp * lchunk) * DD;

    const int warp = tid >> 5, lane = tid & 31;
    const int wm = warp & 1, wn = warp >> 1;
    const int lr = lane >> 2, lc = lane & 3;

    const int k_r   = (2 * tid) >> 5;
    const int k_off = ((2 * tid) & 31) * 4;

    const float* Ag = g_K + base + (size_t)k_r * DD + d0 + k_off;
    const float* Bg = g_V + base + (size_t)k_r * DD + h0 + k_off;

    const uint32_t sA = (uint32_t)__cvta_generic_to_shared(&As[0][0]);
    const uint32_t sB = (uint32_t)__cvta_generic_to_shared(&Bs[0][0]);

    float acc[4][4][4] = {};

    #define KV_ISSUE(st, l0) do {                                              \
        cp16(sA + ((st)*16*BP + k_r*BP + k_off) * 4,     Ag + (size_t)(l0)*DD);      \
        cp16(sA + ((st)*16*BP + k_r*BP + k_off + 4) * 4, Ag + (size_t)(l0)*DD + 4);  \
        cp16(sB + ((st)*16*BP + k_r*BP + k_off) * 4,     Bg + (size_t)(l0)*DD);      \
        cp16(sB + ((st)*16*BP + k_r*BP + k_off + 4) * 4, Bg + (size_t)(l0)*DD + 4);  \
    } while (0)

    #define KV_LDFRAG(af, bf, st, kb) do {                                     \
        _Pragma("unroll")                                                      \
        for (int mt = 0; mt < 4; mt++) {                                       \
            const int m = wm * 64 + mt * 16 + lr;                              \
            af[mt][0] = __float_as_uint(As[st][((kb) + lc)     * BP + m]);     \
            af[mt][1] = __float_as_uint(As[st][((kb) + lc)     * BP + m + 8]); \
            af[mt][2] = __float_as_uint(As[st][((kb) + 4 + lc) * BP + m]);     \
            af[mt][3] = __float_as_uint(As[st][((kb) + 4 + lc) * BP + m + 8]); \
        }                                                                      \
        _Pragma("unroll")                                                      \
        for (int nt = 0; nt < 4; nt++) {                                       \
            const int n = wn * 32 + nt * 8 + lr;                               \
            bf[nt][0] = __float_as_uint(Bs[st][((kb) + lc)     * BP + n]);     \
            bf[nt][1] = __float_as_uint(Bs[st][((kb) + 4 + lc) * BP + n]);     \
        }                                                                      \
    } while (0)

    KV_ISSUE(0, 0);  CP_COMMIT();
    KV_ISSUE(1, 16); CP_COMMIT();
    CP_WAIT1();
    __syncthreads();

    uint32_t af0[4][4], bf0[4][2], af1[4][4], bf1[4][2];
    KV_LDFRAG(af0, bf0, 0, 0);

    const int NST = lchunk / 16;   // 32
    for (int s = 0; s < NST; s++) {
        const int cur = s & 1;
        KV_LDFRAG(af1, bf1, cur, 8);
        mma_sweep(acc, af0, bf0);
        __syncthreads();
        if (s + 2 < NST) { KV_ISSUE(cur, (s + 2) * 16); CP_COMMIT(); }
        mma_sweep(acc, af1, bf1);
        if (s + 1 < NST) {
            if (s + 2 < NST) CP_WAIT1(); else CP_WAIT0();
            __syncthreads();
            KV_LDFRAG(af0, bf0, cur ^ 1, 0);
        }
    }
    #undef KV_ISSUE
    #undef KV_LDFRAG

    float* outp = g_kvpart + (size_t)bz * DD * DD;
    #pragma unroll
    for (int mt = 0; mt < 4; mt++) {
        const int d = d0 + wm * 64 + mt * 16 + lr;
        #pragma unroll
        for (int nt = 0; nt < 4; nt++) {
            const int h = h0 + wn * 32 + nt * 8 + 2 * lc;
            float2 p0 = { acc[mt][nt][0], acc[mt][nt][1] };
            float2 p1 = { acc[mt][nt][2], acc[mt][nt][3] };
            *(float2*)&outp[(size_t)d * DD + h]       = p0;
            *(float2*)&outp[(size_t)(d + 8) * DD + h] = p1;
        }
    }
}

// deterministic reduce + round (natural [d][h])
__global__ void reduce_kv_kernel()
{
    int i = blockIdx.x * blockDim.x + threadIdx.x;
    if (i >= BB * DD * DD) return;
    int b  = i >> 16;
    int dh = i & 65535;
    float s = 0.0f;
    #pragma unroll
    for (int sp = 0; sp < KVS; sp++)
        s += g_kvpart[(size_t)(b * KVS + sp) * DD * DD + dh];
    g_kv[i] = __uint_as_float(f2tf(s));
}

// ============================================================
// out[row,:] = (Q[row,:] @ kv[b]) / z[row]; pre-rounded inputs.
// ============================================================
__global__ __launch_bounds__(256)
void out_mma(float* __restrict__ out)
{
    __shared__ __align__(16) float As[2][128*AP];
    __shared__ __align__(16) float Bs[2][16*BP];

    const int tid  = threadIdx.x;
    const int row0 = blockIdx.y * 128;
    const int col0 = blockIdx.x * 128;
    const int b    = row0 / LL;

    const int warp = tid >> 5, lane = tid & 31;
    const int wm = warp & 1, wn = warp >> 1;
    const int lr = lane >> 2, lc = lane & 3;

    const int a_r   = (2 * tid) >> 2;
    const int a_off = ((2 * tid) & 3) * 4;
    const int b_r   = (2 * tid) >> 5;
    const int b_off = ((2 * tid) & 31) * 4;

    const float* Ag = g_Q + (size_t)(row0 + a_r) * DD + a_off;
    const float* Bg = g_kv + (size_t)b * DD * DD + (size_t)b_r * DD + col0 + b_off;

    const uint32_t sA = (uint32_t)__cvta_generic_to_shared(&As[0][0]);
    const uint32_t sB = (uint32_t)__cvta_generic_to_shared(&Bs[0][0]);

    float acc[4][4][4] = {};

    #define O_ISSUE(st, k0) do {                                               \
        cp16(sA + ((st)*128*AP + a_r*AP + a_off) * 4,     Ag + (k0));          \
        cp16(sA + ((st)*128*AP + a_r*AP + a_off + 4) * 4, Ag + (k0) + 4);      \
        cp16(sB + ((st)*16*BP + b_r*BP + b_off) * 4,      Bg + (size_t)(k0)*DD);     \
        cp16(sB + ((st)*16*BP + b_r*BP + b_off + 4) * 4,  Bg + (size_t)(k0)*DD + 4); \
    } while (0)

    #define O_LDFRAG(af, bf, st, kb) do {                                      \
        _Pragma("unroll")                                                      \
        for (int mt = 0; mt < 4; mt++) {                                       \
            const int m = wm * 64 + mt * 16 + lr;                              \
            af[mt][0] = __float_as_uint(As[st][(m)   * AP + (kb) + lc]);       \
            af[mt][1] = __float_as_uint(As[st][(m+8) * AP + (kb) + lc]);       \
            af[mt][2] = __float_as_uint(As[st][(m)   * AP + (kb) + lc + 4]);   \
            af[mt][3] = __float_as_uint(As[st][(m+8) * AP + (kb) + lc + 4]);   \
        }                                                                      \
        _Pragma("unroll")                                                      \
        for (int nt = 0; nt < 4; nt++) {                                       \
            const int n = wn * 32 + nt * 8 + lr;                               \
            bf[nt][0] = __float_as_uint(Bs[st][((kb) + lc)     * BP + n]);     \
            bf[nt][1] = __float_as_uint(Bs[st][((kb) + 4 + lc) * BP + n]);     \
        }                                                                      \
    } while (0)

    O_ISSUE(0, 0);  CP_COMMIT();
    O_ISSUE(1, 16); CP_COMMIT();
    CP_WAIT1();
    __syncthreads();

    uint32_t af0[4][4], bf0[4][2], af1[4][4], bf1[4][2];
    O_LDFRAG(af0, bf0, 0, 0);

    const int NST = DD / 16;
    for (int s = 0; s < NST; s++) {
        const int cur = s & 1;
        O_LDFRAG(af1, bf1, cur, 8);
        mma_sweep(acc, af0, bf0);
        __syncthreads();
        if (s + 2 < NST) { O_ISSUE(cur, (s + 2) * 16); CP_COMMIT(); }
        mma_sweep(acc, af1, bf1);
        if (s + 1 < NST) {
            if (s + 2 < NST) CP_WAIT1(); else CP_WAIT0();
            __syncthreads();
            O_LDFRAG(af0, bf0, cur ^ 1, 0);
        }
    }
    #undef O_ISSUE
    #undef O_LDFRAG

    #pragma unroll
    for (int mt = 0; mt < 4; mt++) {
        const int r0 = row0 + wm * 64 + mt * 16 + lr;
        const float iz0 = 1.0f / (g_zpart[r0]     + g_zpart[ML + r0]     + 1e-6f);
        const float iz1 = 1.0f / (g_zpart[r0 + 8] + g_zpart[ML + r0 + 8] + 1e-6f);
        #pragma unroll
        for (int nt = 0; nt < 4; nt++) {
            const int c = col0 + wn * 32 + nt * 8 + 2 * lc;
            float2 p0 = { acc[mt][nt][0] * iz0, acc[mt][nt][1] * iz0 };
            float2 p1 = { acc[mt][nt][2] * iz1, acc[mt][nt][3] * iz1 };
            *(float2*)&out[(size_t)r0 * DD + c]       = p0;
            *(float2*)&out[(size_t)(r0 + 8) * DD + c] = p1;
        }
    }
}

// ============================================================
extern "C" void kernel_launch(void* const* d_in, const int* in_sizes, int n_in,
                              void* d_out, int out_size)
{
    const float* q  = (const float*)d_in[0];
    const float* k  = (const float*)d_in[1];
    const float* v  = (const float*)d_in[2];
    const float* Wq = (const float*)d_in[3];
    const float* bq = (const float*)d_in[4];
    const float* Wk = (const float*)d_in[5];
    const float* bk = (const float*)d_in[6];
    const float* Wv = (const float*)d_in[7];
    const float* bv = (const float*)d_in[8];
    float* out = (float*)d_out;

    float *dQ, *dK, *dV, *dWr;
    cudaGetSymbolAddress((void**)&dQ, g_Q);
    cudaGetSymbolAddress((void**)&dK, g_K);
    cudaGetSymbolAddress((void**)&dV, g_V);
    cudaGetSymbolAddress((void**)&dWr, g_Wr);

    // 0. round weights once
    prep_w<<<dim3(256, 3), 256>>>(Wq, Wk, Wv);

    dim3 gProj(DD / 128, ML / 128);

    // 1-2. V (plain), K (+colsum partials)
    proj_mma<0,0><<<gProj, 256>>>(v, dWr + 2 * DD * DD, bv, dV);
    proj_mma<1,1><<<gProj, 256>>>(k, dWr + 1 * DD * DD, bk, dK);

    // 3. ksum
    reduce_kcs_kernel<<<(BB * DD + 255) / 256, 256>>>();

    // 4. Q (+z partials)
    proj_mma<1,2><<<gProj, 256>>>(q, dWr, bq, dQ);

    // 5. kv = K^T V (split-K) + deterministic reduce/round
    dim3 gKV(DD / 128, DD / 128, BB * KVS);
    kv_mma<<<gKV, 256>>>();
    reduce_kv_kernel<<<(BB * DD * DD + 255) / 256, 256>>>();

    // 6. out = (Q @ kv) / z
    dim3 gOut(DD / 128, ML / 128);
    out_mma<<<gOut, 256>>>(out);
}